// round 16
// baseline (speedup 1.0000x reference)
#include <cuda_runtime.h>
#include <cuda_bf16.h>
#include <math.h>
#include <cstdint>

#define BSZ  8
#define CH   256
#define NPIX 4096
#define IMW  64
#define LDA  40   // bf16 elems per smem row (80B, conflict-free ldmatrix)
#define LDB3 264  // proj3 shared-B row width
#define GST  536  // conv B group stride (words)

// ---------------- scratch (device globals; alloc-free) ----------------
__device__ float g_invQ[BSZ*NPIX];
__device__ float g_invK[BSZ*NPIX];
__device__ float g_ksum[BSZ*CH];
__device__ float g_vsum[BSZ*CH];
__device__ float g_kvp[BSZ*4*CH*CH];
__device__ float g_rv[BSZ*CH];
__device__ float g_denom[BSZ*NPIX];
// bf16 operands
__device__ __nv_bfloat16 g_xt[BSZ*NPIX*CH];
__device__ __nv_bfloat16 g_Qt[BSZ*NPIX*CH];     // Q transposed [b][n][c] (written by proj3)
__device__ __nv_bfloat16 g_Kbf[BSZ*CH*NPIX];
__device__ __nv_bfloat16 g_Vbf[BSZ*CH*NPIX];
__device__ __nv_bfloat16 g_Knbf[BSZ*CH*NPIX];
__device__ __nv_bfloat16 g_attnbf[BSZ*CH*NPIX];
__device__ __nv_bfloat16 g_h1bf[BSZ*CH*NPIX];
__device__ __nv_bfloat16 g_Abf[BSZ*CH*CH];
__device__ __nv_bfloat16 g_wqkv[3*CH*CH];
__device__ __nv_bfloat16 g_wc1b[9*CH*CH];
__device__ __nv_bfloat16 g_wc2b[9*CH*CH];

// ================= warp-MMA helpers =================
__device__ __forceinline__ uint32_t smem_u32(const void* p) {
    uint32_t a;
    asm("{ .reg .u64 t; cvta.to.shared.u64 t, %1; cvt.u32.u64 %0, t; }" : "=r"(a) : "l"(p));
    return a;
}
__device__ __forceinline__ void ldsm_x4(uint32_t (&r)[4], uint32_t addr) {
    asm volatile("ldmatrix.sync.aligned.m8n8.x4.shared.b16 {%0,%1,%2,%3}, [%4];"
        : "=r"(r[0]), "=r"(r[1]), "=r"(r[2]), "=r"(r[3]) : "r"(addr));
}
__device__ __forceinline__ void mma16816(float (&d)[4], const uint32_t (&a)[4],
                                         uint32_t b0, uint32_t b1) {
    asm volatile("mma.sync.aligned.m16n8k16.row.col.f32.bf16.bf16.f32 "
        "{%0,%1,%2,%3}, {%4,%5,%6,%7}, {%8,%9}, {%0,%1,%2,%3};"
        : "+f"(d[0]), "+f"(d[1]), "+f"(d[2]), "+f"(d[3])
        : "r"(a[0]), "r"(a[1]), "r"(a[2]), "r"(a[3]), "r"(b0), "r"(b1));
}

// 8-warp (256 thr) chunk: warp = 32M x 64N (kv only)
#define MMA_CHUNK_G(As, AW, Bs, BW, coff, acc, lane, wm, wn) do {                   \
    _Pragma("unroll")                                                               \
    for (int ks = 0; ks < 2; ks++) {                                                \
        uint32_t a_[2][4];                                                          \
        _Pragma("unroll")                                                           \
        for (int mi = 0; mi < 2; mi++)                                              \
            ldsm_x4(a_[mi], smem_u32(&(As)[((wm)*32 + mi*16 + ((lane)&15))*(AW)     \
                                          + ks*16 + ((lane)>>4)*8]));               \
        uint32_t b_[4][4];                                                          \
        _Pragma("unroll")                                                           \
        for (int ni = 0; ni < 4; ni++)                                              \
            ldsm_x4(b_[ni], smem_u32(&(Bs)[((wn)*64 + ni*16 + (((lane)>>4)&1)*8     \
                                            + ((lane)&7))*(BW)                      \
                                           + (coff) + ks*16 + (((lane)>>3)&1)*8])); \
        _Pragma("unroll")                                                           \
        for (int mi = 0; mi < 2; mi++) {                                            \
            _Pragma("unroll")                                                       \
            for (int ni = 0; ni < 4; ni++) {                                        \
                mma16816(acc[mi][ni*2],   a_[mi], b_[ni][0], b_[ni][1]);            \
                mma16816(acc[mi][ni*2+1], a_[mi], b_[ni][2], b_[ni][3]);            \
            }                                                                       \
        }                                                                           \
    }                                                                               \
} while (0)

// 4-warp (128 thr) chunk: warp = 64M x 64N (proj3/attn)
#define MMA_CHUNK4(As, AW, Bs, BW, coff, acc, lane, wm, wn) do {                    \
    _Pragma("unroll")                                                               \
    for (int ks = 0; ks < 2; ks++) {                                                \
        uint32_t a_[4][4];                                                          \
        _Pragma("unroll")                                                           \
        for (int mi = 0; mi < 4; mi++)                                              \
            ldsm_x4(a_[mi], smem_u32(&(As)[((wm)*64 + mi*16 + ((lane)&15))*(AW)     \
                                          + ks*16 + ((lane)>>4)*8]));               \
        uint32_t b_[4][4];                                                          \
        _Pragma("unroll")                                                           \
        for (int ni = 0; ni < 4; ni++)                                              \
            ldsm_x4(b_[ni], smem_u32(&(Bs)[((wn)*64 + ni*16 + (((lane)>>4)&1)*8     \
                                            + ((lane)&7))*(BW)                      \
                                           + (coff) + ks*16 + (((lane)>>3)&1)*8])); \
        _Pragma("unroll")                                                           \
        for (int mi = 0; mi < 4; mi++) {                                            \
            _Pragma("unroll")                                                       \
            for (int ni = 0; ni < 4; ni++) {                                        \
                mma16816(acc[mi][ni*2],   a_[mi], b_[ni][0], b_[ni][1]);            \
                mma16816(acc[mi][ni*2+1], a_[mi], b_[ni][2], b_[ni][3]);            \
            }                                                                       \
        }                                                                           \
    }                                                                               \
} while (0)

#define ACC_ZERO2(acc) do {                                                         \
    _Pragma("unroll")                                                               \
    for (int i_ = 0; i_ < 2; i_++) {                                                \
        _Pragma("unroll")                                                           \
        for (int j_ = 0; j_ < 8; j_++) {                                            \
            _Pragma("unroll")                                                       \
            for (int q_ = 0; q_ < 4; q_++) acc[i_][j_][q_] = 0.f;                   \
        }                                                                           \
    }                                                                               \
} while (0)

#define ACC_ZERO4(acc) do {                                                         \
    _Pragma("unroll")                                                               \
    for (int i_ = 0; i_ < 4; i_++) {                                                \
        _Pragma("unroll")                                                           \
        for (int j_ = 0; j_ < 8; j_++) {                                            \
            _Pragma("unroll")                                                       \
            for (int q_ = 0; q_ < 4; q_++) acc[i_][j_][q_] = 0.f;                   \
        }                                                                           \
    }                                                                               \
} while (0)

// ---------------- k_prep: t_x || cvtw || cvt_wc(c1) || cvt_wc(c2) ----------------
#define PREP_TX   4096
#define PREP_CVTW (PREP_TX + 768)
#define PREP_WC1  (PREP_CVTW + 2304)
#define PREP_TOT  (PREP_WC1 + 2304)
__global__ __launch_bounds__(256) void k_prep(const float* __restrict__ x,
                                              const float* __restrict__ qw,
                                              const float* __restrict__ kw,
                                              const float* __restrict__ vw,
                                              const float* __restrict__ c1w,
                                              const float* __restrict__ c2w)
{
    __shared__ __nv_bfloat16 sm[32][80];
    const int bx = blockIdx.x;
    const int tid = threadIdx.x;
    if (bx < PREP_TX) {
        int nx = bx & 127, cy = (bx >> 7) & 3, b = bx >> 9;
        int c0 = cy*64, n0 = nx*32;
        const float* in = x + ((size_t)b*CH + c0)*NPIX + n0;
        #pragma unroll
        for (int i = 0; i < 8; i++) {
            int e = tid + i*256;
            int c = e >> 5, n = e & 31;
            sm[n][c] = __float2bfloat16(in[(size_t)c*NPIX + n]);
        }
        __syncthreads();
        int n = tid >> 3, seg = tid & 7;
        *(uint4*)(g_xt + ((size_t)b*NPIX + n0+n)*256 + c0 + seg*8) = *(uint4*)&sm[n][seg*8];
    } else if (bx < PREP_CVTW) {
        int i = (bx - PREP_TX)*256 + tid;
        int which = i >> 16, r = i & 65535;
        const float* s = (which == 0) ? qw : (which == 1) ? kw : vw;
        g_wqkv[i] = __float2bfloat16(s[r]);
    } else if (bx < PREP_WC1) {
        int i = (bx - PREP_CVTW)*256 + tid;
        int c = i & 255, o = (i >> 8) & 255, t = i >> 16;
        g_wc1b[i] = __float2bfloat16(c1w[o*2304 + c*9 + t]);
    } else {
        int i = (bx - PREP_WC1)*256 + tid;
        int c = i & 255, o = (i >> 8) & 255, t = i >> 16;
        g_wc2b[i] = __float2bfloat16(c2w[o*2304 + c*9 + t]);
    }
}

// ---------------- k_mid: invK || vsum (vsum has no invK dependency) ----------------
#define MID_IK  64
#define MID_TOT (MID_IK + BSZ*CH)
__global__ __launch_bounds__(256) void k_mid()
{
    const int bx = blockIdx.x;
    const int tid = threadIdx.x;
    if (bx < MID_IK) {
        // invK: 2 tokens/thread
        int idx2 = bx*256 + tid;
        int b = idx2 >> 11, n = (idx2 & 2047) * 2;
        const __nv_bfloat16* Kp = g_Kbf + (size_t)b*CH*NPIX + n;
        float sk0 = 0.f, sk1 = 0.f;
        #pragma unroll 16
        for (int c = 0; c < CH; c++) {
            __nv_bfloat162 k = *(const __nv_bfloat162*)(Kp + (size_t)c*NPIX);
            float kx = __bfloat162float(k.x), ky = __bfloat162float(k.y);
            sk0 = fmaf(kx, kx, sk0);
            sk1 = fmaf(ky, ky, sk1);
        }
        int o = b*NPIX + n;
        g_invK[o]   = 1.0f / sqrtf(sk0);
        g_invK[o+1] = 1.0f / sqrtf(sk1);
    } else {
        // vsum[b,c] = sum_n V (identical summation order to original colsums)
        int bc = bx - MID_IK;
        const __nv_bfloat16* Vp = g_Vbf + (size_t)bc*NPIX;
        float sv = 0.f;
        #pragma unroll
        for (int it = 0; it < 2; it++) {
            int base = (tid + it*256) * 8;
            uint4 vv4 = *(const uint4*)(Vp + base);
            const __nv_bfloat16* vv = (const __nv_bfloat16*)&vv4;
            #pragma unroll
            for (int j = 0; j < 8; j++) sv += __bfloat162float(vv[j]);
        }
        __shared__ float rv[256];
        rv[tid] = sv;
        __syncthreads();
        for (int s = 128; s > 0; s >>= 1) {
            if (tid < s) rv[tid] += rv[tid+s];
            __syncthreads();
        }
        if (tid == 0) g_vsum[bc] = rv[0];
    }
}

// ---------------- fused QKV projection (K, V, then Q -> writes Qt directly) --------
#define P3_BS_BYTES (128*LDB3*2)
#define P3_SMEM     (P3_BS_BYTES + 2*128*LDA*2)
__global__ __launch_bounds__(128) void k_proj3(const __nv_bfloat16* __restrict__ w3,
                                               const float* __restrict__ qb,
                                               const float* __restrict__ kb,
                                               const float* __restrict__ vb,
                                               __nv_bfloat16* __restrict__ outK,
                                               __nv_bfloat16* __restrict__ outV)
{
    extern __shared__ __align__(16) char dsm[];
    __nv_bfloat16* Bs = (__nv_bfloat16*)dsm;
    __nv_bfloat16* As = (__nv_bfloat16*)(dsm + P3_BS_BYTES);
    const int b  = blockIdx.z;
    const int o0 = blockIdx.y * 128;
    const int n0 = blockIdx.x * 128;
    const __nv_bfloat16* xtb = g_xt + (size_t)b*NPIX*CH;
    const int tid = threadIdx.x;
    const int wid = tid >> 5, lane = tid & 31;
    const int wm = wid & 1, wn = wid >> 1;

    #pragma unroll
    for (int i = 0; i < 32; i++) {
        int e = tid + i*128;
        int n = e >> 5, seg = e & 31;
        *(uint4*)&Bs[n*LDB3 + seg*8] = *(const uint4*)(xtb + (size_t)(n0+n)*256 + seg*8);
    }

    float acc[4][8][4];
    const int r0 = lane >> 2, c2 = (lane & 3)*2;

    #pragma unroll
    for (int pass = 0; pass < 3; pass++) {
        const int which = (pass == 0) ? 1 : (pass == 1) ? 2 : 0;
        const __nv_bfloat16* w = w3 + (size_t)which*CH*CH;
        ACC_ZERO4(acc);
        #pragma unroll
        for (int i = 0; i < 4; i++) {
            int e = tid + i*128;
            int o = e >> 2, cq = e & 3;
            *(uint4*)&As[(0*128 + o)*LDA + cq*8] = *(const uint4*)(w + (size_t)(o0+o)*CH + cq*8);
        }
        for (int kc = 0; kc < 8; kc++) {
            __syncthreads();
            int buf = kc & 1;
            if (kc + 1 < 8) {
                int cb = (kc + 1) * 32;
                #pragma unroll
                for (int i = 0; i < 4; i++) {
                    int e = tid + i*128;
                    int o = e >> 2, cq = e & 3;
                    *(uint4*)&As[((buf^1)*128 + o)*LDA + cq*8] =
                        *(const uint4*)(w + (size_t)(o0+o)*CH + cb + cq*8);
                }
            }
            MMA_CHUNK4((As + buf*128*LDA), LDA, Bs, LDB3, kc*32, acc, lane, wm, wn);
        }
        if (pass < 2) {
            const float* bias = (pass == 0) ? kb : vb;
            __nv_bfloat16* ob = ((pass == 0) ? outK : outV) + (size_t)b*CH*NPIX;
            #pragma unroll
            for (int mi = 0; mi < 4; mi++) {
                int o_lo = o0 + wm*64 + mi*16 + r0;
                int o_hi = o_lo + 8;
                float blo = bias[o_lo], bhi = bias[o_hi];
                #pragma unroll
                for (int nj = 0; nj < 8; nj++) {
                    int n = n0 + wn*64 + nj*8 + c2;
                    __nv_bfloat162 vlo, vhi;
                    vlo.x = __float2bfloat16(acc[mi][nj][0] + blo);
                    vlo.y = __float2bfloat16(acc[mi][nj][1] + blo);
                    vhi.x = __float2bfloat16(acc[mi][nj][2] + bhi);
                    vhi.y = __float2bfloat16(acc[mi][nj][3] + bhi);
                    *(__nv_bfloat162*)(ob + (size_t)o_lo*NPIX + n) = vlo;
                    *(__nv_bfloat162*)(ob + (size_t)o_hi*NPIX + n) = vhi;
                }
            }
        } else {
            __syncthreads();
            #pragma unroll
            for (int mi = 0; mi < 4; mi++) {
                int o_lo = wm*64 + mi*16 + r0;
                int o_hi = o_lo + 8;
                float blo = qb[o0 + o_lo], bhi = qb[o0 + o_hi];
                #pragma unroll
                for (int nj = 0; nj < 8; nj++) {
                    int n = wn*64 + nj*8 + c2;
                    Bs[(size_t)n*LDB3 + o_lo]     = __float2bfloat16(acc[mi][nj][0] + blo);
                    Bs[(size_t)(n+1)*LDB3 + o_lo] = __float2bfloat16(acc[mi][nj][1] + blo);
                    Bs[(size_t)n*LDB3 + o_hi]     = __float2bfloat16(acc[mi][nj][2] + bhi);
                    Bs[(size_t)(n+1)*LDB3 + o_hi] = __float2bfloat16(acc[mi][nj][3] + bhi);
                }
            }
            __syncthreads();
            __nv_bfloat16* qt = g_Qt + (size_t)b*NPIX*CH;
            #pragma unroll
            for (int i = 0; i < 16; i++) {
                int e = tid + i*128;
                int n = e >> 4, seg = e & 15;
                *(uint4*)(qt + (size_t)(n0+n)*256 + o0 + seg*8) = *(uint4*)&Bs[(size_t)n*LDB3 + seg*8];
            }
        }
    }
}

// ---------------- ksum; emits normalized Kn bf16 (vsum moved to k_mid) ------------
__global__ __launch_bounds__(256) void k_colsums()
{
    int bc = blockIdx.x;
    int b = bc >> 8;
    const __nv_bfloat16* Kp = g_Kbf + (size_t)bc*NPIX;
    const float* ik = g_invK + (size_t)b*NPIX;
    __nv_bfloat16* knp = g_Knbf + (size_t)bc*NPIX;
    int tid = threadIdx.x;
    float sk = 0.f;
    #pragma unroll
    for (int it = 0; it < 2; it++) {
        int base = (tid + it*256) * 8;
        uint4 kv4 = *(const uint4*)(Kp + base);
        float4 ika = *(const float4*)(ik + base);
        float4 ikb = *(const float4*)(ik + base + 4);
        const __nv_bfloat16* kk = (const __nv_bfloat16*)&kv4;
        float iks[8] = {ika.x, ika.y, ika.z, ika.w, ikb.x, ikb.y, ikb.z, ikb.w};
        unsigned short outw[8];
        #pragma unroll
        for (int j = 0; j < 8; j++) {
            float kn = __bfloat162float(kk[j]) * iks[j];
            __nv_bfloat16 knb = __float2bfloat16(kn);
            outw[j] = __bfloat16_as_ushort(knb);
            sk += kn;
        }
        *(uint4*)(knp + base) = *(uint4*)outw;
    }
    __shared__ float rk[256];
    rk[tid] = sk;
    __syncthreads();
    for (int s = 128; s > 0; s >>= 1) {
        if (tid < s) rk[tid] += rk[tid+s];
        __syncthreads();
    }
    if (tid == 0) g_ksum[bc] = rk[0];
}

// ---------------- k_post: kv GEMM || qstats || rv ----------------
#define POST_KV  128
#define POST_QS  (POST_KV + 1024)
#define POST_TOT (POST_QS + 8)
__global__ __launch_bounds__(256) void k_post(const float* __restrict__ rw)
{
    __shared__ __align__(16) __nv_bfloat16 As[2][128][LDA];
    __shared__ __align__(16) __nv_bfloat16 Bs[2][128][LDA];
    __shared__ float fs[256];
    const int bx = blockIdx.x;
    const int tid = threadIdx.x;
    if (bx < POST_KV) {
        const int c0 = (bx & 1) * 128;
        const int k0 = ((bx >> 1) & 1) * 128;
        const int bsp = bx >> 2;
        const int b = bsp >> 2, sp = bsp & 3;
        const int nb = sp * 1024;
        const __nv_bfloat16* Kn = g_Knbf + (size_t)b*CH*NPIX;
        const __nv_bfloat16* Vb = g_Vbf  + (size_t)b*CH*NPIX;
        const int wid = tid >> 5, lane = tid & 31;
        const int wm = wid & 3, wn = wid >> 2;

        float acc[2][8][4];
        ACC_ZERO2(acc);

        #pragma unroll
        for (int i = 0; i < 16; i++) {
            int e = tid + i*256;
            int r = e >> 5, n = e & 31;
            As[0][r][n] = Kn[(size_t)(k0+r)*NPIX + nb + n];
            Bs[0][r][n] = Vb[(size_t)(c0+r)*NPIX + nb + n];
        }
        for (int kc = 0; kc < 32; kc++) {
            __syncthreads();
            int buf = kc & 1;
            if (kc + 1 < 32) {
                int nn = nb + (kc + 1) * 32;
                #pragma unroll
                for (int i = 0; i < 16; i++) {
                    int e = tid + i*256;
                    int r = e >> 5, n = e & 31;
                    As[buf^1][r][n] = Kn[(size_t)(k0+r)*NPIX + nn + n];
                    Bs[buf^1][r][n] = Vb[(size_t)(c0+r)*NPIX + nn + n];
                }
            }
            MMA_CHUNK_G(&As[buf][0][0], LDA, &Bs[buf][0][0], LDA, 0, acc, lane, wm, wn);
        }
        float* ob = g_kvp + (size_t)bsp*CH*CH;
        const int r0 = lane >> 2, c2 = (lane & 3)*2;
        #pragma unroll
        for (int mi = 0; mi < 2; mi++) {
            int k_lo = k0 + wm*32 + mi*16 + r0;
            int k_hi = k_lo + 8;
            #pragma unroll
            for (int nj = 0; nj < 8; nj++) {
                int c = c0 + wn*64 + nj*8 + c2;
                *(float2*)(ob + (size_t)k_lo*CH + c) = make_float2(acc[mi][nj][0], acc[mi][nj][1]);
                *(float2*)(ob + (size_t)k_hi*CH + c) = make_float2(acc[mi][nj][2], acc[mi][nj][3]);
            }
        }
    } else if (bx < POST_QS) {
        const int bq = bx - POST_KV;
        const int lane = tid & 31, wid = tid >> 5;
        const int b = bq >> 7;
        fs[tid] = g_ksum[b*CH + tid];
        __syncthreads();
        const int t0 = bq*32 + wid*4;
        #pragma unroll
        for (int j = 0; j < 4; j++) {
            int t = t0 + j;
            uint4 v = *(const uint4*)(g_Qt + (size_t)t*256 + lane*8);
            const __nv_bfloat16* qq = (const __nv_bfloat16*)&v;
            float sq = 0.f, dt = 0.f;
            #pragma unroll
            for (int k = 0; k < 8; k++) {
                float f = __bfloat162float(qq[k]);
                sq = fmaf(f, f, sq);
                dt = fmaf(f, fs[lane*8 + k], dt);
            }
            #pragma unroll
            for (int m = 16; m > 0; m >>= 1) {
                sq += __shfl_xor_sync(0xffffffffu, sq, m);
                dt += __shfl_xor_sync(0xffffffffu, dt, m);
            }
            if (lane == 0) {
                float iq = 1.0f / sqrtf(sq);
                g_invQ[t] = iq;
                g_denom[t] = 1.0f / (4096.0f + dt*iq + 1e-6f);
            }
        }
    } else {
        const int b = bx - POST_QS;
        fs[tid] = g_vsum[b*CH + tid];
        __syncthreads();
        float s = 0.f;
        const float* rp = rw + (size_t)tid*CH;
        #pragma unroll 8
        for (int c = 0; c < CH; c++) s = fmaf(rp[c], fs[c], s);
        g_rv[b*CH + tid] = s;
    }
}

// ---------------- A = rw @ kv^T, kvred folded in ----------------
__global__ __launch_bounds__(256) void k_nt(const float* __restrict__ rw,
                                            __nv_bfloat16* __restrict__ out)
{
    __shared__ float As[32][65];
    __shared__ float Bs[32][65];
    const int b = blockIdx.z;
    const int i0 = blockIdx.y*64, j0 = blockIdx.x*64;
    const float* P = g_kvp + (size_t)b*4*65536;
    const int tid = threadIdx.x;
    const int ty = tid >> 4, tx = tid & 15;
    float acc[4][4];
    #pragma unroll
    for (int i = 0; i < 4; i++) {
        #pragma unroll
        for (int j = 0; j < 4; j++) acc[i][j] = 0.f;
    }

    for (int l0 = 0; l0 < CH; l0 += 32) {
        #pragma unroll
        for (int r = 0; r < 8; r++) {
            int e = tid + r*256;
            int ii = e >> 5, ll = e & 31;
            As[ll][ii] = rw[(size_t)(i0+ii)*CH + l0 + ll];
        }
        #pragma unroll
        for (int r = 0; r < 8; r++) {
            int e = tid + r*256;
            int jj = e >> 5, ll = e & 31;
            size_t off = (size_t)(j0+jj)*CH + l0 + ll;
            Bs[ll][jj] = (P[off] + P[65536 + off]) + (P[2*65536 + off] + P[3*65536 + off]);
        }
        __syncthreads();
        #pragma unroll
        for (int ll = 0; ll < 32; ll++) {
            float ar[4], br[4];
            #pragma unroll
            for (int i = 0; i < 4; i++) ar[i] = As[ll][ty*4+i];
            #pragma unroll
            for (int j = 0; j < 4; j++) br[j] = Bs[ll][tx*4+j];
            #pragma unroll
            for (int i = 0; i < 4; i++) {
                #pragma unroll
                for (int j = 0; j < 4; j++)
                    acc[i][j] = fmaf(ar[i], br[j], acc[i][j]);
            }
        }
        __syncthreads();
    }
    __nv_bfloat16* ob = out + (size_t)b*CH*CH;
    #pragma unroll
    for (int i = 0; i < 4; i++) {
        #pragma unroll
        for (int j = 0; j < 4; j++)
            ob[(size_t)(i0+ty*4+i)*CH + j0 + tx*4 + j] = __float2bfloat16(acc[i][j]);
    }
}

// ---------------- bf16 MMA attn GEMM: 128 threads, 64x64 warp tiles ----------------
__global__ __launch_bounds__(128) void k_attn_tc(const float* __restrict__ rb)
{
    __shared__ __align__(16) __nv_bfloat16 As[2][128][LDA];
    __shared__ __align__(16) __nv_bfloat16 Bs[2][128][LDA];
    const int b  = blockIdx.z;
    const int o0 = blockIdx.y * 128;
    const int n0 = blockIdx.x * 128;
    const __nv_bfloat16* Am = g_Abf + (size_t)b*CH*CH;
    const __nv_bfloat16* Qt = g_Qt + (size_t)b*NPIX*CH;
    const int tid = threadIdx.x;
    const int wid = tid >> 5, lane = tid & 31;
    const int wm = wid & 1, wn = wid >> 1;

    float acc[4][8][4];
    ACC_ZERO4(acc);

    #pragma unroll
    for (int i = 0; i < 4; i++) {
        int e = tid + i*128;
        int o = e >> 2, cq = e & 3;
        *(uint4*)&As[0][o][cq*8] = *(const uint4*)(Am + (size_t)(o0+o)*CH + cq*8);
    }
    #pragma unroll
    for (int i = 0; i < 4; i++) {
        int e = tid + i*128;
        int n = e >> 2, cq = e & 3;
        *(uint4*)&Bs[0][n][cq*8] = *(const uint4*)(Qt + (size_t)(n0+n)*256 + cq*8);
    }

    for (int kc = 0; kc < 8; kc++) {
        __syncthreads();
        int buf = kc & 1;
        if (kc + 1 < 8) {
            int cb = (kc + 1) * 32;
            #pragma unroll
            for (int i = 0; i < 4; i++) {
                int e = tid + i*128;
                int o = e >> 2, cq = e & 3;
                *(uint4*)&As[buf^1][o][cq*8] = *(const uint4*)(Am + (size_t)(o0+o)*CH + cb + cq*8);
            }
            #pragma unroll
            for (int i = 0; i < 4; i++) {
                int e = tid + i*128;
                int n = e >> 2, cq = e & 3;
                *(uint4*)&Bs[buf^1][n][cq*8] = *(const uint4*)(Qt + (size_t)(n0+n)*256 + cb + cq*8);
            }
        }
        MMA_CHUNK4(&As[buf][0][0], LDA, &Bs[buf][0][0], LDA, 0, acc, lane, wm, wn);
    }

    __nv_bfloat16* ob = g_attnbf + (size_t)b*CH*NPIX;
    const int r0 = lane >> 2, c2 = (lane & 3)*2;
    #pragma unroll
    for (int mi = 0; mi < 4; mi++) {
        int o_lo = o0 + wm*64 + mi*16 + r0;
        int o_hi = o_lo + 8;
        float rvlo = g_rv[b*CH + o_lo], rvhi = g_rv[b*CH + o_hi];
        float rblo = rb[o_lo], rbhi = rb[o_hi];
        #pragma unroll
        for (int nj = 0; nj < 8; nj++) {
            int n = n0 + wn*64 + nj*8 + c2;
            float iq0 = g_invQ[b*NPIX + n],     dn0 = g_denom[b*NPIX + n];
            float iq1 = g_invQ[b*NPIX + n + 1], dn1 = g_denom[b*NPIX + n + 1];
            __nv_bfloat162 vlo, vhi;
            vlo.x = __float2bfloat16(fmaf(fmaf(iq0, acc[mi][nj][0], rvlo), dn0, rblo));
            vlo.y = __float2bfloat16(fmaf(fmaf(iq1, acc[mi][nj][1], rvlo), dn1, rblo));
            vhi.x = __float2bfloat16(fmaf(fmaf(iq0, acc[mi][nj][2], rvhi), dn0, rbhi));
            vhi.y = __float2bfloat16(fmaf(fmaf(iq1, acc[mi][nj][3], rvhi), dn1, rbhi));
            *(__nv_bfloat162*)(ob + (size_t)o_lo*NPIX + n) = vlo;
            *(__nv_bfloat162*)(ob + (size_t)o_hi*NPIX + n) = vhi;
        }
    }
}

// ---------------- bf16 MMA 3x3 conv: 4 warps, 64x64 warp tiles ----------------
#define CONV_BW_WORDS (8*GST)
#define CONV_A_BYTES  (9*128*LDA*2)
#define CONV_SMEM     (CONV_A_BYTES + CONV_BW_WORDS*4)

__device__ __forceinline__ void conv_fillB4(uint32_t* __restrict__ Bw,
                                            const __nv_bfloat16* __restrict__ inb,
                                            int cbase, int pr0, int tid)
{
    #pragma unroll
    for (int it = 0; it < 4; it++) {
        int e = tid + it*128;
        int kw = e >> 5;
        int row = (e >> 3) & 3;
        int seg = e & 7;
        int g = (kw & 3) + ((kw >> 3) << 2);
        int s = (kw >> 2) & 1;
        int gr = pr0 - 1 + row;
        uint32_t* dst = Bw + g*GST + (row*66 + 1 + seg*8)*2 + s;
        if ((unsigned)gr < IMW) {
            const __nv_bfloat16* q = inb + (size_t)(cbase + kw*2)*NPIX + gr*IMW + seg*8;
            uint4 lo4 = *(const uint4*)q;
            uint4 hi4 = *(const uint4*)(q + NPIX);
            const unsigned short* ls = (const unsigned short*)&lo4;
            const unsigned short* hs = (const unsigned short*)&hi4;
            #pragma unroll
            for (int j = 0; j < 8; j++)
                dst[j*2] = (uint32_t)ls[j] | ((uint32_t)hs[j] << 16);
        } else {
            #pragma unroll
            for (int j = 0; j < 8; j++) dst[j*2] = 0u;
        }
    }
}

__global__ __launch_bounds__(128) void k_conv_tc(const __nv_bfloat16* __restrict__ in,
                                                 const __nv_bfloat16* __restrict__ wt,
                                                 const float* __restrict__ bias,
                                                 const float* __restrict__ xres,
                                                 float* __restrict__ out_f,
                                                 __nv_bfloat16* __restrict__ out_bf,
                                                 int fuse)
{
    extern __shared__ __align__(16) char dsm[];
    __nv_bfloat16* Asm = (__nv_bfloat16*)dsm;
    uint32_t* Bw = (uint32_t*)(dsm + CONV_A_BYTES);
    const int b   = blockIdx.z;
    const int o0  = blockIdx.y * 128;
    const int pr0 = blockIdx.x * 2;
    const __nv_bfloat16* inb = in + (size_t)b*CH*NPIX;
    const int tid = threadIdx.x;
    const int wid = tid >> 5, lane = tid & 31;
    const int wm = wid & 1;
    const int wn = wid >> 1;

    float acc[4][8][4];
    ACC_ZERO4(acc);

    {
        int kw = tid >> 3;
        int row = (tid >> 1) & 3;
        int side = tid & 1;
        int g = (kw & 3) + ((kw >> 3) << 2);
        int s = (kw >> 2) & 1;
        Bw[g*GST + (row*66 + side*65)*2 + s] = 0u;
    }

    for (int cb = 0; cb < 8; cb++) {
        __syncthreads();
        #pragma unroll
        for (int i = 0; i < 36; i++) {
            int e = tid + i*128;
            int t = e >> 9;
            int rem = e & 511;
            int o = rem >> 2, cq = rem & 3;
            *(uint4*)(Asm + ((size_t)t*128 + o)*LDA + cq*8) =
                *(const uint4*)(wt + ((size_t)t*256 + o0 + o)*256 + cb*32 + cq*8);
        }
        conv_fillB4(Bw, inb, cb*32, pr0, tid);
        __syncthreads();
        #pragma unroll
        for (int t = 0; t < 9; t++) {
            const int dy = t / 3 - 1, dx = t % 3 - 1;
            const int pos0 = (1 + wn + dy) * 66 + 1 + dx;
            #pragma unroll
            for (int ks = 0; ks < 2; ks++) {
                uint32_t a_[4][4];
                #pragma unroll
                for (int mi = 0; mi < 4; mi++)
                    ldsm_x4(a_[mi], smem_u32(Asm + ((size_t)t*128 + wm*64 + mi*16 + (lane&15))*LDA
                                             + ks*16 + (lane>>4)*8));
                const uint32_t* bp = Bw + ((lane&3) + ks*4)*GST
                                   + (pos0 + (lane>>2))*2;
                #pragma unroll
                for (int f = 0; f < 8; f++) {
                    uint2 bb = *(const uint2*)(bp + f*16);
                    #pragma unroll
                    for (int mi = 0; mi < 4; mi++)
                        mma16816(acc[mi][f], a_[mi], bb.x, bb.y);
                }
            }
        }
    }

    const int r0 = lane >> 2, c2 = (lane & 3)*2;
    const int pxbase = pr0*64;
    if (fuse) {
        const float* xb = xres + (size_t)b*CH*NPIX;
        float* ob = out_f + (size_t)b*CH*NPIX;
        #pragma unroll
        for (int mi = 0; mi < 4; mi++) {
            int o_lo = o0 + wm*64 + mi*16 + r0;
            int o_hi = o_lo + 8;
            float blo = bias[o_lo], bhi = bias[o_hi];
            #pragma unroll
            for (int f = 0; f < 8; f++) {
                int px = pxbase + wn*64 + f*8 + c2;
                float a0 = acc[mi][f][0] + blo, a1 = acc[mi][f][1] + blo;
                float a2 = acc[mi][f][2] + bhi, a3 = acc[mi][f][3] + bhi;
                float2 xlo = *(const float2*)(xb + (size_t)o_lo*NPIX + px);
                float2 xhi = *(const float2*)(xb + (size_t)o_hi*NPIX + px);
                a0 = fmaf(a0, xlo.x, xlo.x);
                a1 = fmaf(a1, xlo.y, xlo.y);
                a2 = fmaf(a2, xhi.x, xhi.x);
                a3 = fmaf(a3, xhi.y, xhi.y);
                *(float2*)(ob + (size_t)o_lo*NPIX + px) = make_float2(a0, a1);
                *(float2*)(ob + (size_t)o_hi*NPIX + px) = make_float2(a2, a3);
            }
        }
    } else {
        __nv_bfloat16* ob = out_bf + (size_t)b*CH*NPIX;
        #pragma unroll
        for (int mi = 0; mi < 4; mi++) {
            int o_lo = o0 + wm*64 + mi*16 + r0;
            int o_hi = o_lo + 8;
            float blo = bias[o_lo], bhi = bias[o_hi];
            #pragma unroll
            for (int f = 0; f < 8; f++) {
                int px = pxbase + wn*64 + f*8 + c2;
                __nv_bfloat162 vlo, vhi;
                vlo.x = __float2bfloat16(acc[mi][f][0] + blo);
                vlo.y = __float2bfloat16(acc[mi][f][1] + blo);
                vhi.x = __float2bfloat16(acc[mi][f][2] + bhi);
                vhi.y = __float2bfloat16(acc[mi][f][3] + bhi);
                *(__nv_bfloat162*)(ob + (size_t)o_lo*NPIX + px) = vlo;
                *(__nv_bfloat162*)(ob + (size_t)o_hi*NPIX + px) = vhi;
            }
        }
    }
}

// ---------------- launcher ----------------
extern "C" void kernel_launch(void* const* d_in, const int* in_sizes, int n_in,
                              void* d_out, int out_size)
{
    (void)in_sizes; (void)n_in; (void)out_size;
    const float* x   = (const float*)d_in[0];
    const float* qw  = (const float*)d_in[1];
    const float* qb  = (const float*)d_in[2];
    const float* kw  = (const float*)d_in[3];
    const float* kb  = (const float*)d_in[4];
    const float* vw  = (const float*)d_in[5];
    const float* vb  = (const float*)d_in[6];
    const float* rw  = (const float*)d_in[7];
    const float* rb  = (const float*)d_in[8];
    const float* c1w = (const float*)d_in[9];
    const float* c1b = (const float*)d_in[10];
    const float* c2w = (const float*)d_in[11];
    const float* c2b = (const float*)d_in[12];
    float* out = (float*)d_out;

    __nv_bfloat16 *pKbf, *pVbf, *pattnbf, *ph1bf, *pAbf, *pwqkv, *pwc1, *pwc2;
    cudaGetSymbolAddress((void**)&pKbf,   g_Kbf);
    cudaGetSymbolAddress((void**)&pVbf,   g_Vbf);
    cudaGetSymbolAddress((void**)&pattnbf,g_attnbf);
    cudaGetSymbolAddress((void**)&ph1bf,  g_h1bf);
    cudaGetSymbolAddress((void**)&pAbf,   g_Abf);
    cudaGetSymbolAddress((void**)&pwqkv,  g_wqkv);
    cudaGetSymbolAddress((void**)&pwc1,   g_wc1b);
    cudaGetSymbolAddress((void**)&pwc2,   g_wc2b);

    static int attr_set = 0;
    if (!attr_set) {
        cudaFuncSetAttribute(k_proj3,   cudaFuncAttributeMaxDynamicSharedMemorySize, P3_SMEM);
        cudaFuncSetAttribute(k_conv_tc, cudaFuncAttributeMaxDynamicSharedMemorySize, CONV_SMEM);
        attr_set = 1;
    }

    dim3 gproj(32, 2, BSZ);
    dim3 gnt(4, 4, BSZ);
    dim3 gconv(32, 2, BSZ);

    k_prep<<<PREP_TOT, 256>>>(x, qw, kw, vw, c1w, c2w);
    k_proj3<<<gproj, 128, P3_SMEM>>>(pwqkv, qb, kb, vb, pKbf, pVbf);
    k_mid<<<MID_TOT, 256>>>();
    k_colsums<<<BSZ*CH, 256>>>();
    k_post<<<POST_TOT, 256>>>(rw);
    k_nt<<<gnt, 256>>>(rw, pAbf);
    k_attn_tc<<<gproj, 128>>>(rb);
    k_conv_tc<<<gconv, 128, CONV_SMEM>>>(pattnbf, pwc1, c1b, (const float*)0, (float*)0, ph1bf, 0);
    k_conv_tc<<<gconv, 128, CONV_SMEM>>>(ph1bf, pwc2, c2b, x, out, (__nv_bfloat16*)0, 1);
}

// round 17
// speedup vs baseline: 1.0371x; 1.0371x over previous
#include <cuda_runtime.h>
#include <cuda_bf16.h>
#include <math.h>
#include <cstdint>

#define BSZ  8
#define CH   256
#define NPIX 4096
#define IMW  64
#define LDA  40   // bf16 elems per smem row (80B, conflict-free ldmatrix)
#define LDB3 264  // proj3 shared-B row width
#define GST  536  // conv B group stride (words)

// ---------------- scratch (device globals; alloc-free) ----------------
__device__ float g_invQ[BSZ*NPIX];
__device__ float g_invK[BSZ*NPIX];
__device__ float g_ksum[BSZ*CH];
__device__ float g_vsum[BSZ*CH];
__device__ float g_kvp[BSZ*4*CH*CH];
__device__ float g_rv[BSZ*CH];
__device__ float g_denom[BSZ*NPIX];
// bf16 operands
__device__ __nv_bfloat16 g_xt[BSZ*NPIX*CH];
__device__ __nv_bfloat16 g_Qt[BSZ*NPIX*CH];     // Q transposed [b][n][c] (written by proj3)
__device__ __nv_bfloat16 g_Kbf[BSZ*CH*NPIX];
__device__ __nv_bfloat16 g_Vbf[BSZ*CH*NPIX];
__device__ __nv_bfloat16 g_Knbf[BSZ*CH*NPIX];
__device__ __nv_bfloat16 g_attnbf[BSZ*CH*NPIX];
__device__ __nv_bfloat16 g_h1bf[BSZ*CH*NPIX];
__device__ __nv_bfloat16 g_Abf[BSZ*CH*CH];
__device__ __nv_bfloat16 g_wqkv[3*CH*CH];
__device__ __nv_bfloat16 g_wc1b[9*CH*CH];
__device__ __nv_bfloat16 g_wc2b[9*CH*CH];

// ================= warp-MMA helpers =================
__device__ __forceinline__ uint32_t smem_u32(const void* p) {
    uint32_t a;
    asm("{ .reg .u64 t; cvta.to.shared.u64 t, %1; cvt.u32.u64 %0, t; }" : "=r"(a) : "l"(p));
    return a;
}
__device__ __forceinline__ void ldsm_x4(uint32_t (&r)[4], uint32_t addr) {
    asm volatile("ldmatrix.sync.aligned.m8n8.x4.shared.b16 {%0,%1,%2,%3}, [%4];"
        : "=r"(r[0]), "=r"(r[1]), "=r"(r[2]), "=r"(r[3]) : "r"(addr));
}
__device__ __forceinline__ void mma16816(float (&d)[4], const uint32_t (&a)[4],
                                         uint32_t b0, uint32_t b1) {
    asm volatile("mma.sync.aligned.m16n8k16.row.col.f32.bf16.bf16.f32 "
        "{%0,%1,%2,%3}, {%4,%5,%6,%7}, {%8,%9}, {%0,%1,%2,%3};"
        : "+f"(d[0]), "+f"(d[1]), "+f"(d[2]), "+f"(d[3])
        : "r"(a[0]), "r"(a[1]), "r"(a[2]), "r"(a[3]), "r"(b0), "r"(b1));
}
#define CP_ASYNC16(saddr, gptr) \
    asm volatile("cp.async.cg.shared.global [%0], [%1], 16;" :: "r"(saddr), "l"(gptr))
#define CP_ASYNC_WAIT() \
    asm volatile("cp.async.commit_group;\ncp.async.wait_group 0;" ::: "memory")

// 8-warp (256 thr) chunk: warp = 32M x 64N (kv only)
#define MMA_CHUNK_G(As, AW, Bs, BW, coff, acc, lane, wm, wn) do {                   \
    _Pragma("unroll")                                                               \
    for (int ks = 0; ks < 2; ks++) {                                                \
        uint32_t a_[2][4];                                                          \
        _Pragma("unroll")                                                           \
        for (int mi = 0; mi < 2; mi++)                                              \
            ldsm_x4(a_[mi], smem_u32(&(As)[((wm)*32 + mi*16 + ((lane)&15))*(AW)     \
                                          + ks*16 + ((lane)>>4)*8]));               \
        uint32_t b_[4][4];                                                          \
        _Pragma("unroll")                                                           \
        for (int ni = 0; ni < 4; ni++)                                              \
            ldsm_x4(b_[ni], smem_u32(&(Bs)[((wn)*64 + ni*16 + (((lane)>>4)&1)*8     \
                                            + ((lane)&7))*(BW)                      \
                                           + (coff) + ks*16 + (((lane)>>3)&1)*8])); \
        _Pragma("unroll")                                                           \
        for (int mi = 0; mi < 2; mi++) {                                            \
            _Pragma("unroll")                                                       \
            for (int ni = 0; ni < 4; ni++) {                                        \
                mma16816(acc[mi][ni*2],   a_[mi], b_[ni][0], b_[ni][1]);            \
                mma16816(acc[mi][ni*2+1], a_[mi], b_[ni][2], b_[ni][3]);            \
            }                                                                       \
        }                                                                           \
    }                                                                               \
} while (0)

// 4-warp (128 thr) chunk: warp = 64M x 64N (proj3/attn)
#define MMA_CHUNK4(As, AW, Bs, BW, coff, acc, lane, wm, wn) do {                    \
    _Pragma("unroll")                                                               \
    for (int ks = 0; ks < 2; ks++) {                                                \
        uint32_t a_[4][4];                                                          \
        _Pragma("unroll")                                                           \
        for (int mi = 0; mi < 4; mi++)                                              \
            ldsm_x4(a_[mi], smem_u32(&(As)[((wm)*64 + mi*16 + ((lane)&15))*(AW)     \
                                          + ks*16 + ((lane)>>4)*8]));               \
        uint32_t b_[4][4];                                                          \
        _Pragma("unroll")                                                           \
        for (int ni = 0; ni < 4; ni++)                                              \
            ldsm_x4(b_[ni], smem_u32(&(Bs)[((wn)*64 + ni*16 + (((lane)>>4)&1)*8     \
                                            + ((lane)&7))*(BW)                      \
                                           + (coff) + ks*16 + (((lane)>>3)&1)*8])); \
        _Pragma("unroll")                                                           \
        for (int mi = 0; mi < 4; mi++) {                                            \
            _Pragma("unroll")                                                       \
            for (int ni = 0; ni < 4; ni++) {                                        \
                mma16816(acc[mi][ni*2],   a_[mi], b_[ni][0], b_[ni][1]);            \
                mma16816(acc[mi][ni*2+1], a_[mi], b_[ni][2], b_[ni][3]);            \
            }                                                                       \
        }                                                                           \
    }                                                                               \
} while (0)

#define ACC_ZERO2(acc) do {                                                         \
    _Pragma("unroll")                                                               \
    for (int i_ = 0; i_ < 2; i_++) {                                                \
        _Pragma("unroll")                                                           \
        for (int j_ = 0; j_ < 8; j_++) {                                            \
            _Pragma("unroll")                                                       \
            for (int q_ = 0; q_ < 4; q_++) acc[i_][j_][q_] = 0.f;                   \
        }                                                                           \
    }                                                                               \
} while (0)

#define ACC_ZERO4(acc) do {                                                         \
    _Pragma("unroll")                                                               \
    for (int i_ = 0; i_ < 4; i_++) {                                                \
        _Pragma("unroll")                                                           \
        for (int j_ = 0; j_ < 8; j_++) {                                            \
            _Pragma("unroll")                                                       \
            for (int q_ = 0; q_ < 4; q_++) acc[i_][j_][q_] = 0.f;                   \
        }                                                                           \
    }                                                                               \
} while (0)

// ---------------- k_prep: t_x || cvtw || cvt_wc(c1) || cvt_wc(c2) ----------------
#define PREP_TX   4096
#define PREP_CVTW (PREP_TX + 768)
#define PREP_WC1  (PREP_CVTW + 2304)
#define PREP_TOT  (PREP_WC1 + 2304)
__global__ __launch_bounds__(256) void k_prep(const float* __restrict__ x,
                                              const float* __restrict__ qw,
                                              const float* __restrict__ kw,
                                              const float* __restrict__ vw,
                                              const float* __restrict__ c1w,
                                              const float* __restrict__ c2w)
{
    __shared__ __nv_bfloat16 sm[32][80];
    const int bx = blockIdx.x;
    const int tid = threadIdx.x;
    if (bx < PREP_TX) {
        int nx = bx & 127, cy = (bx >> 7) & 3, b = bx >> 9;
        int c0 = cy*64, n0 = nx*32;
        const float* in = x + ((size_t)b*CH + c0)*NPIX + n0;
        #pragma unroll
        for (int i = 0; i < 8; i++) {
            int e = tid + i*256;
            int c = e >> 5, n = e & 31;
            sm[n][c] = __float2bfloat16(in[(size_t)c*NPIX + n]);
        }
        __syncthreads();
        int n = tid >> 3, seg = tid & 7;
        *(uint4*)(g_xt + ((size_t)b*NPIX + n0+n)*256 + c0 + seg*8) = *(uint4*)&sm[n][seg*8];
    } else if (bx < PREP_CVTW) {
        int i = (bx - PREP_TX)*256 + tid;
        int which = i >> 16, r = i & 65535;
        const float* s = (which == 0) ? qw : (which == 1) ? kw : vw;
        g_wqkv[i] = __float2bfloat16(s[r]);
    } else if (bx < PREP_WC1) {
        int i = (bx - PREP_CVTW)*256 + tid;
        int c = i & 255, o = (i >> 8) & 255, t = i >> 16;
        g_wc1b[i] = __float2bfloat16(c1w[o*2304 + c*9 + t]);
    } else {
        int i = (bx - PREP_WC1)*256 + tid;
        int c = i & 255, o = (i >> 8) & 255, t = i >> 16;
        g_wc2b[i] = __float2bfloat16(c2w[o*2304 + c*9 + t]);
    }
}

// ---------------- k_mid: invK (128 blocks x 128 threads, 2 tokens/thread) ---------
__global__ __launch_bounds__(128) void k_mid()
{
    int idx2 = blockIdx.x*128 + threadIdx.x;
    int b = idx2 >> 11, n = (idx2 & 2047) * 2;
    const __nv_bfloat16* Kp = g_Kbf + (size_t)b*CH*NPIX + n;
    float sk0 = 0.f, sk1 = 0.f;
    #pragma unroll 16
    for (int c = 0; c < CH; c++) {
        __nv_bfloat162 k = *(const __nv_bfloat162*)(Kp + (size_t)c*NPIX);
        float kx = __bfloat162float(k.x), ky = __bfloat162float(k.y);
        sk0 = fmaf(kx, kx, sk0);
        sk1 = fmaf(ky, ky, sk1);
    }
    int o = b*NPIX + n;
    g_invK[o]   = 1.0f / sqrtf(sk0);
    g_invK[o+1] = 1.0f / sqrtf(sk1);
}

// ---------------- fused QKV projection (K, V, then Q -> writes Qt directly) --------
#define P3_BS_BYTES (128*LDB3*2)
#define P3_SMEM     (P3_BS_BYTES + 2*128*LDA*2)
__global__ __launch_bounds__(128) void k_proj3(const __nv_bfloat16* __restrict__ w3,
                                               const float* __restrict__ qb,
                                               const float* __restrict__ kb,
                                               const float* __restrict__ vb,
                                               __nv_bfloat16* __restrict__ outK,
                                               __nv_bfloat16* __restrict__ outV)
{
    extern __shared__ __align__(16) char dsm[];
    __nv_bfloat16* Bs = (__nv_bfloat16*)dsm;
    __nv_bfloat16* As = (__nv_bfloat16*)(dsm + P3_BS_BYTES);
    const int b  = blockIdx.z;
    const int o0 = blockIdx.y * 128;
    const int n0 = blockIdx.x * 128;
    const __nv_bfloat16* xtb = g_xt + (size_t)b*NPIX*CH;
    const int tid = threadIdx.x;
    const int wid = tid >> 5, lane = tid & 31;
    const int wm = wid & 1, wn = wid >> 1;

    #pragma unroll
    for (int i = 0; i < 32; i++) {
        int e = tid + i*128;
        int n = e >> 5, seg = e & 31;
        *(uint4*)&Bs[n*LDB3 + seg*8] = *(const uint4*)(xtb + (size_t)(n0+n)*256 + seg*8);
    }

    float acc[4][8][4];
    const int r0 = lane >> 2, c2 = (lane & 3)*2;

    #pragma unroll
    for (int pass = 0; pass < 3; pass++) {
        const int which = (pass == 0) ? 1 : (pass == 1) ? 2 : 0;
        const __nv_bfloat16* w = w3 + (size_t)which*CH*CH;
        ACC_ZERO4(acc);
        #pragma unroll
        for (int i = 0; i < 4; i++) {
            int e = tid + i*128;
            int o = e >> 2, cq = e & 3;
            *(uint4*)&As[(0*128 + o)*LDA + cq*8] = *(const uint4*)(w + (size_t)(o0+o)*CH + cq*8);
        }
        for (int kc = 0; kc < 8; kc++) {
            __syncthreads();
            int buf = kc & 1;
            if (kc + 1 < 8) {
                int cb = (kc + 1) * 32;
                #pragma unroll
                for (int i = 0; i < 4; i++) {
                    int e = tid + i*128;
                    int o = e >> 2, cq = e & 3;
                    *(uint4*)&As[((buf^1)*128 + o)*LDA + cq*8] =
                        *(const uint4*)(w + (size_t)(o0+o)*CH + cb + cq*8);
                }
            }
            MMA_CHUNK4((As + buf*128*LDA), LDA, Bs, LDB3, kc*32, acc, lane, wm, wn);
        }
        if (pass < 2) {
            const float* bias = (pass == 0) ? kb : vb;
            __nv_bfloat16* ob = ((pass == 0) ? outK : outV) + (size_t)b*CH*NPIX;
            #pragma unroll
            for (int mi = 0; mi < 4; mi++) {
                int o_lo = o0 + wm*64 + mi*16 + r0;
                int o_hi = o_lo + 8;
                float blo = bias[o_lo], bhi = bias[o_hi];
                #pragma unroll
                for (int nj = 0; nj < 8; nj++) {
                    int n = n0 + wn*64 + nj*8 + c2;
                    __nv_bfloat162 vlo, vhi;
                    vlo.x = __float2bfloat16(acc[mi][nj][0] + blo);
                    vlo.y = __float2bfloat16(acc[mi][nj][1] + blo);
                    vhi.x = __float2bfloat16(acc[mi][nj][2] + bhi);
                    vhi.y = __float2bfloat16(acc[mi][nj][3] + bhi);
                    *(__nv_bfloat162*)(ob + (size_t)o_lo*NPIX + n) = vlo;
                    *(__nv_bfloat162*)(ob + (size_t)o_hi*NPIX + n) = vhi;
                }
            }
        } else {
            __syncthreads();
            #pragma unroll
            for (int mi = 0; mi < 4; mi++) {
                int o_lo = wm*64 + mi*16 + r0;
                int o_hi = o_lo + 8;
                float blo = qb[o0 + o_lo], bhi = qb[o0 + o_hi];
                #pragma unroll
                for (int nj = 0; nj < 8; nj++) {
                    int n = wn*64 + nj*8 + c2;
                    Bs[(size_t)n*LDB3 + o_lo]     = __float2bfloat16(acc[mi][nj][0] + blo);
                    Bs[(size_t)(n+1)*LDB3 + o_lo] = __float2bfloat16(acc[mi][nj][1] + blo);
                    Bs[(size_t)n*LDB3 + o_hi]     = __float2bfloat16(acc[mi][nj][2] + bhi);
                    Bs[(size_t)(n+1)*LDB3 + o_hi] = __float2bfloat16(acc[mi][nj][3] + bhi);
                }
            }
            __syncthreads();
            __nv_bfloat16* qt = g_Qt + (size_t)b*NPIX*CH;
            #pragma unroll
            for (int i = 0; i < 16; i++) {
                int e = tid + i*128;
                int n = e >> 4, seg = e & 15;
                *(uint4*)(qt + (size_t)(n0+n)*256 + o0 + seg*8) = *(uint4*)&Bs[(size_t)n*LDB3 + seg*8];
            }
        }
    }
}

// ---------------- ksum / vsum; emits normalized Kn bf16 ----------------
__global__ __launch_bounds__(256) void k_colsums()
{
    int bc = blockIdx.x;
    int b = bc >> 8;
    const __nv_bfloat16* Kp = g_Kbf + (size_t)bc*NPIX;
    const __nv_bfloat16* Vp = g_Vbf + (size_t)bc*NPIX;
    const float* ik = g_invK + (size_t)b*NPIX;
    __nv_bfloat16* knp = g_Knbf + (size_t)bc*NPIX;
    int tid = threadIdx.x;
    float sk = 0.f, sv = 0.f;
    #pragma unroll
    for (int it = 0; it < 2; it++) {
        int base = (tid + it*256) * 8;
        uint4 kv4 = *(const uint4*)(Kp + base);
        uint4 vv4 = *(const uint4*)(Vp + base);
        float4 ika = *(const float4*)(ik + base);
        float4 ikb = *(const float4*)(ik + base + 4);
        const __nv_bfloat16* kk = (const __nv_bfloat16*)&kv4;
        const __nv_bfloat16* vv = (const __nv_bfloat16*)&vv4;
        float iks[8] = {ika.x, ika.y, ika.z, ika.w, ikb.x, ikb.y, ikb.z, ikb.w};
        unsigned short outw[8];
        #pragma unroll
        for (int j = 0; j < 8; j++) {
            float kn = __bfloat162float(kk[j]) * iks[j];
            __nv_bfloat16 knb = __float2bfloat16(kn);
            outw[j] = __bfloat16_as_ushort(knb);
            sk += kn;
            sv += __bfloat162float(vv[j]);
        }
        *(uint4*)(knp + base) = *(uint4*)outw;
    }
    __shared__ float rk[256], rv[256];
    rk[tid] = sk; rv[tid] = sv;
    __syncthreads();
    for (int s = 128; s > 0; s >>= 1) {
        if (tid < s) { rk[tid] += rk[tid+s]; rv[tid] += rv[tid+s]; }
        __syncthreads();
    }
    if (tid == 0) { g_ksum[bc] = rk[0]; g_vsum[bc] = rv[0]; }
}

// ---------------- k_post: kv GEMM || qstats || rv ----------------
#define POST_KV  128
#define POST_QS  (POST_KV + 1024)
#define POST_TOT (POST_QS + 8)
__global__ __launch_bounds__(256) void k_post(const float* __restrict__ rw)
{
    __shared__ __align__(16) __nv_bfloat16 As[2][128][LDA];
    __shared__ __align__(16) __nv_bfloat16 Bs[2][128][LDA];
    __shared__ float fs[256];
    const int bx = blockIdx.x;
    const int tid = threadIdx.x;
    if (bx < POST_KV) {
        const int c0 = (bx & 1) * 128;
        const int k0 = ((bx >> 1) & 1) * 128;
        const int bsp = bx >> 2;
        const int b = bsp >> 2, sp = bsp & 3;
        const int nb = sp * 1024;
        const __nv_bfloat16* Kn = g_Knbf + (size_t)b*CH*NPIX;
        const __nv_bfloat16* Vb = g_Vbf  + (size_t)b*CH*NPIX;
        const int wid = tid >> 5, lane = tid & 31;
        const int wm = wid & 3, wn = wid >> 2;

        float acc[2][8][4];
        ACC_ZERO2(acc);

        #pragma unroll
        for (int i = 0; i < 16; i++) {
            int e = tid + i*256;
            int r = e >> 5, n = e & 31;
            As[0][r][n] = Kn[(size_t)(k0+r)*NPIX + nb + n];
            Bs[0][r][n] = Vb[(size_t)(c0+r)*NPIX + nb + n];
        }
        for (int kc = 0; kc < 32; kc++) {
            __syncthreads();
            int buf = kc & 1;
            if (kc + 1 < 32) {
                int nn = nb + (kc + 1) * 32;
                #pragma unroll
                for (int i = 0; i < 16; i++) {
                    int e = tid + i*256;
                    int r = e >> 5, n = e & 31;
                    As[buf^1][r][n] = Kn[(size_t)(k0+r)*NPIX + nn + n];
                    Bs[buf^1][r][n] = Vb[(size_t)(c0+r)*NPIX + nn + n];
                }
            }
            MMA_CHUNK_G(&As[buf][0][0], LDA, &Bs[buf][0][0], LDA, 0, acc, lane, wm, wn);
        }
        float* ob = g_kvp + (size_t)bsp*CH*CH;
        const int r0 = lane >> 2, c2 = (lane & 3)*2;
        #pragma unroll
        for (int mi = 0; mi < 2; mi++) {
            int k_lo = k0 + wm*32 + mi*16 + r0;
            int k_hi = k_lo + 8;
            #pragma unroll
            for (int nj = 0; nj < 8; nj++) {
                int c = c0 + wn*64 + nj*8 + c2;
                *(float2*)(ob + (size_t)k_lo*CH + c) = make_float2(acc[mi][nj][0], acc[mi][nj][1]);
                *(float2*)(ob + (size_t)k_hi*CH + c) = make_float2(acc[mi][nj][2], acc[mi][nj][3]);
            }
        }
    } else if (bx < POST_QS) {
        const int bq = bx - POST_KV;
        const int lane = tid & 31, wid = tid >> 5;
        const int b = bq >> 7;
        fs[tid] = g_ksum[b*CH + tid];
        __syncthreads();
        const int t0 = bq*32 + wid*4;
        #pragma unroll
        for (int j = 0; j < 4; j++) {
            int t = t0 + j;
            uint4 v = *(const uint4*)(g_Qt + (size_t)t*256 + lane*8);
            const __nv_bfloat16* qq = (const __nv_bfloat16*)&v;
            float sq = 0.f, dt = 0.f;
            #pragma unroll
            for (int k = 0; k < 8; k++) {
                float f = __bfloat162float(qq[k]);
                sq = fmaf(f, f, sq);
                dt = fmaf(f, fs[lane*8 + k], dt);
            }
            #pragma unroll
            for (int m = 16; m > 0; m >>= 1) {
                sq += __shfl_xor_sync(0xffffffffu, sq, m);
                dt += __shfl_xor_sync(0xffffffffu, dt, m);
            }
            if (lane == 0) {
                float iq = 1.0f / sqrtf(sq);
                g_invQ[t] = iq;
                g_denom[t] = 1.0f / (4096.0f + dt*iq + 1e-6f);
            }
        }
    } else {
        const int b = bx - POST_QS;
        fs[tid] = g_vsum[b*CH + tid];
        __syncthreads();
        float s = 0.f;
        const float* rp = rw + (size_t)tid*CH;
        #pragma unroll 8
        for (int c = 0; c < CH; c++) s = fmaf(rp[c], fs[c], s);
        g_rv[b*CH + tid] = s;
    }
}

// ---------------- A = rw @ kv^T, kvred folded in ----------------
__global__ __launch_bounds__(256) void k_nt(const float* __restrict__ rw,
                                            __nv_bfloat16* __restrict__ out)
{
    __shared__ float As[32][65];
    __shared__ float Bs[32][65];
    const int b = blockIdx.z;
    const int i0 = blockIdx.y*64, j0 = blockIdx.x*64;
    const float* P = g_kvp + (size_t)b*4*65536;
    const int tid = threadIdx.x;
    const int ty = tid >> 4, tx = tid & 15;
    float acc[4][4];
    #pragma unroll
    for (int i = 0; i < 4; i++) {
        #pragma unroll
        for (int j = 0; j < 4; j++) acc[i][j] = 0.f;
    }

    for (int l0 = 0; l0 < CH; l0 += 32) {
        #pragma unroll
        for (int r = 0; r < 8; r++) {
            int e = tid + r*256;
            int ii = e >> 5, ll = e & 31;
            As[ll][ii] = rw[(size_t)(i0+ii)*CH + l0 + ll];
        }
        #pragma unroll
        for (int r = 0; r < 8; r++) {
            int e = tid + r*256;
            int jj = e >> 5, ll = e & 31;
            size_t off = (size_t)(j0+jj)*CH + l0 + ll;
            Bs[ll][jj] = (P[off] + P[65536 + off]) + (P[2*65536 + off] + P[3*65536 + off]);
        }
        __syncthreads();
        #pragma unroll
        for (int ll = 0; ll < 32; ll++) {
            float ar[4], br[4];
            #pragma unroll
            for (int i = 0; i < 4; i++) ar[i] = As[ll][ty*4+i];
            #pragma unroll
            for (int j = 0; j < 4; j++) br[j] = Bs[ll][tx*4+j];
            #pragma unroll
            for (int i = 0; i < 4; i++) {
                #pragma unroll
                for (int j = 0; j < 4; j++)
                    acc[i][j] = fmaf(ar[i], br[j], acc[i][j]);
            }
        }
        __syncthreads();
    }
    __nv_bfloat16* ob = out + (size_t)b*CH*CH;
    #pragma unroll
    for (int i = 0; i < 4; i++) {
        #pragma unroll
        for (int j = 0; j < 4; j++)
            ob[(size_t)(i0+ty*4+i)*CH + j0 + tx*4 + j] = __float2bfloat16(acc[i][j]);
    }
}

// ---------------- bf16 MMA attn GEMM: 128 threads, 64x64 warp tiles ----------------
__global__ __launch_bounds__(128) void k_attn_tc(const float* __restrict__ rb)
{
    __shared__ __align__(16) __nv_bfloat16 As[2][128][LDA];
    __shared__ __align__(16) __nv_bfloat16 Bs[2][128][LDA];
    const int b  = blockIdx.z;
    const int o0 = blockIdx.y * 128;
    const int n0 = blockIdx.x * 128;
    const __nv_bfloat16* Am = g_Abf + (size_t)b*CH*CH;
    const __nv_bfloat16* Qt = g_Qt + (size_t)b*NPIX*CH;
    const int tid = threadIdx.x;
    const int wid = tid >> 5, lane = tid & 31;
    const int wm = wid & 1, wn = wid >> 1;

    float acc[4][8][4];
    ACC_ZERO4(acc);

    #pragma unroll
    for (int i = 0; i < 4; i++) {
        int e = tid + i*128;
        int o = e >> 2, cq = e & 3;
        *(uint4*)&As[0][o][cq*8] = *(const uint4*)(Am + (size_t)(o0+o)*CH + cq*8);
    }
    #pragma unroll
    for (int i = 0; i < 4; i++) {
        int e = tid + i*128;
        int n = e >> 2, cq = e & 3;
        *(uint4*)&Bs[0][n][cq*8] = *(const uint4*)(Qt + (size_t)(n0+n)*256 + cq*8);
    }

    for (int kc = 0; kc < 8; kc++) {
        __syncthreads();
        int buf = kc & 1;
        if (kc + 1 < 8) {
            int cb = (kc + 1) * 32;
            #pragma unroll
            for (int i = 0; i < 4; i++) {
                int e = tid + i*128;
                int o = e >> 2, cq = e & 3;
                *(uint4*)&As[buf^1][o][cq*8] = *(const uint4*)(Am + (size_t)(o0+o)*CH + cb + cq*8);
            }
            #pragma unroll
            for (int i = 0; i < 4; i++) {
                int e = tid + i*128;
                int n = e >> 2, cq = e & 3;
                *(uint4*)&Bs[buf^1][n][cq*8] = *(const uint4*)(Qt + (size_t)(n0+n)*256 + cb + cq*8);
            }
        }
        MMA_CHUNK4(&As[buf][0][0], LDA, &Bs[buf][0][0], LDA, 0, acc, lane, wm, wn);
    }

    __nv_bfloat16* ob = g_attnbf + (size_t)b*CH*NPIX;
    const int r0 = lane >> 2, c2 = (lane & 3)*2;
    #pragma unroll
    for (int mi = 0; mi < 4; mi++) {
        int o_lo = o0 + wm*64 + mi*16 + r0;
        int o_hi = o_lo + 8;
        float rvlo = g_rv[b*CH + o_lo], rvhi = g_rv[b*CH + o_hi];
        float rblo = rb[o_lo], rbhi = rb[o_hi];
        #pragma unroll
        for (int nj = 0; nj < 8; nj++) {
            int n = n0 + wn*64 + nj*8 + c2;
            float iq0 = g_invQ[b*NPIX + n],     dn0 = g_denom[b*NPIX + n];
            float iq1 = g_invQ[b*NPIX + n + 1], dn1 = g_denom[b*NPIX + n + 1];
            __nv_bfloat162 vlo, vhi;
            vlo.x = __float2bfloat16(fmaf(fmaf(iq0, acc[mi][nj][0], rvlo), dn0, rblo));
            vlo.y = __float2bfloat16(fmaf(fmaf(iq1, acc[mi][nj][1], rvlo), dn1, rblo));
            vhi.x = __float2bfloat16(fmaf(fmaf(iq0, acc[mi][nj][2], rvhi), dn0, rbhi));
            vhi.y = __float2bfloat16(fmaf(fmaf(iq1, acc[mi][nj][3], rvhi), dn1, rbhi));
            *(__nv_bfloat162*)(ob + (size_t)o_lo*NPIX + n) = vlo;
            *(__nv_bfloat162*)(ob + (size_t)o_hi*NPIX + n) = vhi;
        }
    }
}

// ---------------- bf16 MMA 3x3 conv: 4 warps, 64x64 tiles, cp.async A-fill --------
#define CONV_BW_WORDS (8*GST)
#define CONV_A_BYTES  (9*128*LDA*2)
#define CONV_SMEM     (CONV_A_BYTES + CONV_BW_WORDS*4)

__device__ __forceinline__ void conv_fillB4(uint32_t* __restrict__ Bw,
                                            const __nv_bfloat16* __restrict__ inb,
                                            int cbase, int pr0, int tid)
{
    #pragma unroll
    for (int it = 0; it < 4; it++) {
        int e = tid + it*128;
        int kw = e >> 5;
        int row = (e >> 3) & 3;
        int seg = e & 7;
        int g = (kw & 3) + ((kw >> 3) << 2);
        int s = (kw >> 2) & 1;
        int gr = pr0 - 1 + row;
        uint32_t* dst = Bw + g*GST + (row*66 + 1 + seg*8)*2 + s;
        if ((unsigned)gr < IMW) {
            const __nv_bfloat16* q = inb + (size_t)(cbase + kw*2)*NPIX + gr*IMW + seg*8;
            uint4 lo4 = *(const uint4*)q;
            uint4 hi4 = *(const uint4*)(q + NPIX);
            const unsigned short* ls = (const unsigned short*)&lo4;
            const unsigned short* hs = (const unsigned short*)&hi4;
            #pragma unroll
            for (int j = 0; j < 8; j++)
                dst[j*2] = (uint32_t)ls[j] | ((uint32_t)hs[j] << 16);
        } else {
            #pragma unroll
            for (int j = 0; j < 8; j++) dst[j*2] = 0u;
        }
    }
}

__global__ __launch_bounds__(128) void k_conv_tc(const __nv_bfloat16* __restrict__ in,
                                                 const __nv_bfloat16* __restrict__ wt,
                                                 const float* __restrict__ bias,
                                                 const float* __restrict__ xres,
                                                 float* __restrict__ out_f,
                                                 __nv_bfloat16* __restrict__ out_bf,
                                                 int fuse)
{
    extern __shared__ __align__(16) char dsm[];
    __nv_bfloat16* Asm = (__nv_bfloat16*)dsm;
    uint32_t* Bw = (uint32_t*)(dsm + CONV_A_BYTES);
    const int b   = blockIdx.z;
    const int o0  = blockIdx.y * 128;
    const int pr0 = blockIdx.x * 2;
    const __nv_bfloat16* inb = in + (size_t)b*CH*NPIX;
    const int tid = threadIdx.x;
    const int wid = tid >> 5, lane = tid & 31;
    const int wm = wid & 1;
    const int wn = wid >> 1;

    float acc[4][8][4];
    ACC_ZERO4(acc);

    {
        int kw = tid >> 3;
        int row = (tid >> 1) & 3;
        int side = tid & 1;
        int g = (kw & 3) + ((kw >> 3) << 2);
        int s = (kw >> 2) & 1;
        Bw[g*GST + (row*66 + side*65)*2 + s] = 0u;
    }

    for (int cb = 0; cb < 8; cb++) {
        __syncthreads();
        // A fill via cp.async (overlaps with B fill below)
        #pragma unroll
        for (int i = 0; i < 36; i++) {
            int e = tid + i*128;
            int t = e >> 9;
            int rem = e & 511;
            int o = rem >> 2, cq = rem & 3;
            CP_ASYNC16(smem_u32(Asm + ((size_t)t*128 + o)*LDA + cq*8),
                       wt + ((size_t)t*256 + o0 + o)*256 + cb*32 + cq*8);
        }
        conv_fillB4(Bw, inb, cb*32, pr0, tid);
        CP_ASYNC_WAIT();
        __syncthreads();
        #pragma unroll
        for (int t = 0; t < 9; t++) {
            const int dy = t / 3 - 1, dx = t % 3 - 1;
            const int pos0 = (1 + wn + dy) * 66 + 1 + dx;
            #pragma unroll
            for (int ks = 0; ks < 2; ks++) {
                uint32_t a_[4][4];
                #pragma unroll
                for (int mi = 0; mi < 4; mi++)
                    ldsm_x4(a_[mi], smem_u32(Asm + ((size_t)t*128 + wm*64 + mi*16 + (lane&15))*LDA
                                             + ks*16 + (lane>>4)*8));
                const uint32_t* bp = Bw + ((lane&3) + ks*4)*GST
                                   + (pos0 + (lane>>2))*2;
                #pragma unroll
                for (int f = 0; f < 8; f++) {
                    uint2 bb = *(const uint2*)(bp + f*16);
                    #pragma unroll
                    for (int mi = 0; mi < 4; mi++)
                        mma16816(acc[mi][f], a_[mi], bb.x, bb.y);
                }
            }
        }
    }

    const int r0 = lane >> 2, c2 = (lane & 3)*2;
    const int pxbase = pr0*64;
    if (fuse) {
        const float* xb = xres + (size_t)b*CH*NPIX;
        float* ob = out_f + (size_t)b*CH*NPIX;
        #pragma unroll
        for (int mi = 0; mi < 4; mi++) {
            int o_lo = o0 + wm*64 + mi*16 + r0;
            int o_hi = o_lo + 8;
            float blo = bias[o_lo], bhi = bias[o_hi];
            #pragma unroll
            for (int f = 0; f < 8; f++) {
                int px = pxbase + wn*64 + f*8 + c2;
                float a0 = acc[mi][f][0] + blo, a1 = acc[mi][f][1] + blo;
                float a2 = acc[mi][f][2] + bhi, a3 = acc[mi][f][3] + bhi;
                float2 xlo = *(const float2*)(xb + (size_t)o_lo*NPIX + px);
                float2 xhi = *(const float2*)(xb + (size_t)o_hi*NPIX + px);
                a0 = fmaf(a0, xlo.x, xlo.x);
                a1 = fmaf(a1, xlo.y, xlo.y);
                a2 = fmaf(a2, xhi.x, xhi.x);
                a3 = fmaf(a3, xhi.y, xhi.y);
                *(float2*)(ob + (size_t)o_lo*NPIX + px) = make_float2(a0, a1);
                *(float2*)(ob + (size_t)o_hi*NPIX + px) = make_float2(a2, a3);
            }
        }
    } else {
        __nv_bfloat16* ob = out_bf + (size_t)b*CH*NPIX;
        #pragma unroll
        for (int mi = 0; mi < 4; mi++) {
            int o_lo = o0 + wm*64 + mi*16 + r0;
            int o_hi = o_lo + 8;
            float blo = bias[o_lo], bhi = bias[o_hi];
            #pragma unroll
            for (int f = 0; f < 8; f++) {
                int px = pxbase + wn*64 + f*8 + c2;
                __nv_bfloat162 vlo, vhi;
                vlo.x = __float2bfloat16(acc[mi][f][0] + blo);
                vlo.y = __float2bfloat16(acc[mi][f][1] + blo);
                vhi.x = __float2bfloat16(acc[mi][f][2] + bhi);
                vhi.y = __float2bfloat16(acc[mi][f][3] + bhi);
                *(__nv_bfloat162*)(ob + (size_t)o_lo*NPIX + px) = vlo;
                *(__nv_bfloat162*)(ob + (size_t)o_hi*NPIX + px) = vhi;
            }
        }
    }
}

// ---------------- launcher ----------------
extern "C" void kernel_launch(void* const* d_in, const int* in_sizes, int n_in,
                              void* d_out, int out_size)
{
    (void)in_sizes; (void)n_in; (void)out_size;
    const float* x   = (const float*)d_in[0];
    const float* qw  = (const float*)d_in[1];
    const float* qb  = (const float*)d_in[2];
    const float* kw  = (const float*)d_in[3];
    const float* kb  = (const float*)d_in[4];
    const float* vw  = (const float*)d_in[5];
    const float* vb  = (const float*)d_in[6];
    const float* rw  = (const float*)d_in[7];
    const float* rb  = (const float*)d_in[8];
    const float* c1w = (const float*)d_in[9];
    const float* c1b = (const float*)d_in[10];
    const float* c2w = (const float*)d_in[11];
    const float* c2b = (const float*)d_in[12];
    float* out = (float*)d_out;

    __nv_bfloat16 *pKbf, *pVbf, *pattnbf, *ph1bf, *pAbf, *pwqkv, *pwc1, *pwc2;
    cudaGetSymbolAddress((void**)&pKbf,   g_Kbf);
    cudaGetSymbolAddress((void**)&pVbf,   g_Vbf);
    cudaGetSymbolAddress((void**)&pattnbf,g_attnbf);
    cudaGetSymbolAddress((void**)&ph1bf,  g_h1bf);
    cudaGetSymbolAddress((void**)&pAbf,   g_Abf);
    cudaGetSymbolAddress((void**)&pwqkv,  g_wqkv);
    cudaGetSymbolAddress((void**)&pwc1,   g_wc1b);
    cudaGetSymbolAddress((void**)&pwc2,   g_wc2b);

    static int attr_set = 0;
    if (!attr_set) {
        cudaFuncSetAttribute(k_proj3,   cudaFuncAttributeMaxDynamicSharedMemorySize, P3_SMEM);
        cudaFuncSetAttribute(k_conv_tc, cudaFuncAttributeMaxDynamicSharedMemorySize, CONV_SMEM);
        attr_set = 1;
    }

    dim3 gproj(32, 2, BSZ);
    dim3 gnt(4, 4, BSZ);
    dim3 gconv(32, 2, BSZ);

    k_prep<<<PREP_TOT, 256>>>(x, qw, kw, vw, c1w, c2w);
    k_proj3<<<gproj, 128, P3_SMEM>>>(pwqkv, qb, kb, vb, pKbf, pVbf);
    k_mid<<<128, 128>>>();
    k_colsums<<<BSZ*CH, 256>>>();
    k_post<<<POST_TOT, 256>>>(rw);
    k_nt<<<gnt, 256>>>(rw, pAbf);
    k_attn_tc<<<gproj, 128>>>(rb);
    k_conv_tc<<<gconv, 128, CONV_SMEM>>>(pattnbf, pwc1, c1b, (const float*)0, (float*)0, ph1bf, 0);
    k_conv_tc<<<gconv, 128, CONV_SMEM>>>(ph1bf, pwc2, c2b, x, out, (__nv_bfloat16*)0, 1);
}